// round 6
// baseline (speedup 1.0000x reference)
#include <cuda_runtime.h>
#include <cuda_fp16.h>
#include <cstddef>

// ForwardSim, fully tensorized (mma.sync HMMA, 3-term fp16 split everywhere).
// R6: GEMM1 (env @ W1e, K=16 zero-padded from 9) runs on the tensor pipe with
// accumulators initialized from fragment-native projAcc smem; its D-fragment
// IS GEMM2's A-fragment (relu+split in regs, no smem round trip). One
// 512-thread CTA per SM (kM=256, grid=128) for 16-warp latency hiding.

using u32 = unsigned int;
using u64 = unsigned long long;

namespace {
constexpr int kB = 32768, kT = 50, kH = 128, kM = 256, kThreads = 512;

constexpr int OFF_BFRAG = 0;        // 65536: W2 frags [ch][kb][nf][lane] 16B
constexpr int OFF_PACC  = 65536;    // 131072: projAcc frags [m16][nf][lane] 16B fp32
constexpr int OFF_W1EB  = 196608;   // 8192: W1e B-frags [nf16][lane] 16B
constexpr int OFF_ENV   = 204800;   // 13312: 256 x 13 f32
constexpr int OFF_BW    = 218112;   // 1024: (b2 pair, W3 pair) per col pair
constexpr int OFF_PART  = 219136;   // 2048: 2 x 256 partials
constexpr int OFF_SC    = 221184;   // 64
constexpr int SMEM_BYTES = 221248;
constexpr int OFF_W1P   = 0;        // phase alias in BFRAG: W1[0:64] natural
} // namespace

__device__ __forceinline__ u64 pack_dup(float v) {
    u64 r; asm("mov.b64 %0, {%1, %1};" : "=l"(r) : "f"(v)); return r;
}
__device__ __forceinline__ u64 pack2(float a, float b) {
    u64 r; asm("mov.b64 %0, {%1, %2};" : "=l"(r) : "f"(a), "f"(b)); return r;
}
__device__ __forceinline__ void unpack2(u64 v, float& a, float& b) {
    asm("mov.b64 {%0, %1}, %2;" : "=f"(a), "=f"(b) : "l"(v));
}
__device__ __forceinline__ u64 fma2(u64 a, u64 b, u64 c) {
    u64 d; asm("fma.rn.f32x2 %0, %1, %2, %3;" : "=l"(d) : "l"(a), "l"(b), "l"(c));
    return d;
}
__device__ __forceinline__ void split2(float f0, float f1, u32& hi, u32& lo) {
    __half h0 = __float2half_rn(f0), h1 = __float2half_rn(f1);
    __half2 hh = __halves2half2(h0, h1);
    hi = reinterpret_cast<u32&>(hh);
    __half2 ll = __floats2half2_rn(f0 - __half2float(h0),
                                   f1 - __half2float(h1));
    lo = reinterpret_cast<u32&>(ll);
}
__device__ __forceinline__ void mma16816(float d[4], u32 a0, u32 a1, u32 a2,
                                         u32 a3, u32 b0, u32 b1) {
    asm volatile(
        "mma.sync.aligned.m16n8k16.row.col.f32.f16.f16.f32 "
        "{%0,%1,%2,%3}, {%4,%5,%6,%7}, {%8,%9}, {%0,%1,%2,%3};"
        : "+f"(d[0]), "+f"(d[1]), "+f"(d[2]), "+f"(d[3])
        : "r"(a0), "r"(a1), "r"(a2), "r"(a3), "r"(b0), "r"(b1));
}

__global__ void __launch_bounds__(kThreads, 1)
fsim_mma(const float* __restrict__ proj, const float* __restrict__ idm,
         const float* __restrict__ merg, const float* __restrict__ W1,
         const float* __restrict__ b1,   const float* __restrict__ W2,
         const float* __restrict__ b2,   const float* __restrict__ W3,
         const float* __restrict__ b3,   const float* __restrict__ smean,
         const float* __restrict__ svar, float* __restrict__ out)
{
    extern __shared__ char smem[];
    float* smf = (float*)smem;

    const int tid = threadIdx.x, wid = tid >> 5, lane = tid & 31;
    const int mbW = wid >> 1, ch = wid & 1, g = lane >> 2, q = lane & 3;
    const int rowBase = blockIdx.x * kM;

    // ---------------- phase A: stage W1[0:64] natural + small tables -------
    for (int i = tid; i < 64 * kH; i += kThreads)
        smf[(OFF_W1P >> 2) + i] = W1[i];
    if (tid < 64) {
        int c = tid * 2;
        float4 v;
        v.x = b2[c]; v.y = b2[c + 1]; v.z = W3[c]; v.w = W3[c + 1];
        *(float4*)(smem + OFF_BW + tid * 16) = v;
    }
    if (tid < 6) {
        smf[(OFF_SC >> 2) + tid]     = smean[tid];
        smf[(OFF_SC >> 2) + 8 + tid] = rsqrtf(svar[tid]);
    }
    __syncthreads();

    // -------- phase B: projAcc = proj@W1[:64]+b1 -> fragment-native fp32 ---
    for (int task = tid; task < 2048; task += kThreads) {
        int r = task >> 3, cg = task & 7;   // row, 16-col group
        const float* prow = proj + (size_t)(rowBase + r) * 64;
        u64 acc[8];
        #pragma unroll
        for (int e = 0; e < 8; e++)
            acc[e] = pack2(__ldg(&b1[cg * 16 + 2 * e]),
                           __ldg(&b1[cg * 16 + 2 * e + 1]));
        #pragma unroll 4
        for (int k4 = 0; k4 < 16; k4++) {
            float4 av = __ldg((const float4*)(prow + k4 * 4));
            float avv[4] = {av.x, av.y, av.z, av.w};
            #pragma unroll
            for (int e2 = 0; e2 < 4; e2++) {
                u64 a = pack_dup(avv[e2]);
                const u64* w = (const u64*)
                    &smf[(OFF_W1P >> 2) + (k4 * 4 + e2) * 128 + cg * 16];
                #pragma unroll
                for (int e = 0; e < 8; e++) acc[e] = fma2(a, w[e], acc[e]);
            }
        }
        int m16 = r >> 4, half = (r >> 3) & 1, lrow = r & 7;
        #pragma unroll
        for (int e = 0; e < 8; e++) {
            int nf = cg * 2 + (e >> 2);
            int ln = lrow * 4 + (e & 3);
            float lo_, hi_;
            unpack2(acc[e], lo_, hi_);
            *(float2*)(smem + OFF_PACC +
                       (size_t)(((m16 * 16 + nf) * 32 + ln) * 16) + half * 8)
                = make_float2(lo_, hi_);
        }
    }
    __syncthreads();

    // -------- phase C: W2 -> fragment fp16 hi/lo (overwrites W1P) ----------
    for (int i = tid; i < 4096; i += kThreads) {
        int t  = i & 31, nf = (i >> 5) & 7, kb = (i >> 8) & 7, c2 = (i >> 11) & 1;
        int gg = t >> 2, qq = t & 3;
        int n  = c2 * 64 + nf * 8 + gg;
        int k0 = kb * 16 + qq * 2;
        float w00 = W2[(size_t)k0 * 128 + n];
        float w01 = W2[(size_t)(k0 + 1) * 128 + n];
        float w10 = W2[(size_t)(k0 + 8) * 128 + n];
        float w11 = W2[(size_t)(k0 + 9) * 128 + n];
        u32 h0, l0, h1v, l1v;
        split2(w00, w01, h0, l0);
        split2(w10, w11, h1v, l1v);
        ulonglong2 e;
        e.x = ((u64)h1v << 32) | h0;
        e.y = ((u64)l1v << 32) | l0;
        *(ulonglong2*)(smem + OFF_BFRAG +
                       (size_t)(((c2 * 8 + kb) * 8 + nf) * 32 + t) * 16) = e;
    }
    // -------- phase C2: W1e (rows 64..72 of W1) -> B-frags, K=16 padded ----
    {
        int t = tid & 31, nf = tid >> 5;     // nf 0..15
        int gg = t >> 2, qq = t & 3;
        int n  = nf * 8 + gg;
        int k0 = qq * 2;
        float w00 = W1[(size_t)(64 + k0) * 128 + n];
        float w01 = W1[(size_t)(64 + k0 + 1) * 128 + n];
        float w10 = (qq == 0) ? W1[(size_t)72 * 128 + n] : 0.f;  // k=8 only
        u32 h0, l0, h1v, l1v;
        split2(w00, w01, h0, l0);
        split2(w10, 0.f, h1v, l1v);
        ulonglong2 e;
        e.x = ((u64)h1v << 32) | h0;
        e.y = ((u64)l1v << 32) | l0;
        *(ulonglong2*)(smem + OFF_W1EB + (size_t)(nf * 32 + t) * 16) = e;
    }
    __syncthreads();

    const float b3v = __ldg(&b3[0]);
    float ego_v = 0.f, ego_x = 0.f, act_c = 0.f;   // carry in tid<256

    // ================= timestep loop =================
    for (int t = 0; t < kT; t++) {
        // ---- env features (one thread per row) ----
        if (tid < kM) {
            const float* sp = idm + (size_t)(rowBase + tid) * (kT * 12) + t * 12;
            float4 a0 = *(const float4*)sp;
            float4 a1 = *(const float4*)(sp + 4);
            float s11 = sp[11];
            if (t == 0) { ego_v = a0.x; ego_x = a0.w; }
            else {
                ego_v = fmaf(act_c, 0.1f, ego_v);
                ego_x = ego_x + ego_v * 0.1f + act_c * 0.005f;
            }
            float ev[6];
            ev[0] = ego_v;
            ev[1] = a0.y;
            ev[2] = ego_v - a0.y;
            ev[3] = a1.x - ego_x;
            ev[4] = (ego_v - a0.z) * s11;
            ev[5] = (a1.y - ego_x) * s11 + (1.0f - s11) * 100.0f;
            #pragma unroll
            for (int j = 0; j < 6; j++)
                smf[(OFF_ENV >> 2) + tid * 13 + j] =
                    (ev[j] - smf[(OFF_SC >> 2) + j]) * smf[(OFF_SC >> 2) + 8 + j];
            const float* mp = merg + (size_t)(rowBase + tid) * (kT * 3) + t * 3;
            smf[(OFF_ENV >> 2) + tid * 13 + 6] = mp[0];
            smf[(OFF_ENV >> 2) + tid * 13 + 7] = mp[1];
            smf[(OFF_ENV >> 2) + tid * 13 + 8] = mp[2];
        }
        __syncthreads();

        // ---- env A-fragments for this warp's 4 row-slots ----
        // i = m*2 + p : row = mbW*32 + m*16 + p*8 + g
        u32 ehi[4], elo[4], fhi[4], flo[4];
        #pragma unroll
        for (int i = 0; i < 4; i++) {
            int rr = mbW * 32 + (i >> 1) * 16 + ((i & 1) << 3) + g;
            const float* ep = &smf[(OFF_ENV >> 2) + rr * 13];
            float e0 = ep[2 * q], e1 = ep[2 * q + 1];
            float e8 = (q == 0) ? ep[8] : 0.f;
            split2(e0, e1, ehi[i], elo[i]);
            split2(e8, 0.f, fhi[i], flo[i]);
        }

        float d[2][8][4];
        #pragma unroll
        for (int m = 0; m < 2; m++)
            #pragma unroll
            for (int nf = 0; nf < 8; nf++)
                d[m][nf][0] = d[m][nf][1] = d[m][nf][2] = d[m][nf][3] = 0.f;

        for (int kb = 0; kb < 8; kb++) {
            u32 Ah[2][4], Al[2][4];
            // GEMM1: pre = projAcc + env @ W1e -> relu/split -> A-frags
            #pragma unroll
            for (int m = 0; m < 2; m++) {
                #pragma unroll
                for (int nfo = 0; nfo < 2; nfo++) {
                    int nf1 = kb * 2 + nfo;
                    float4 pv = *(const float4*)(smem + OFF_PACC +
                        (size_t)((((mbW * 2 + m) * 16 + nf1) * 32 + lane) * 16));
                    float dd[4] = {pv.x, pv.y, pv.z, pv.w};
                    ulonglong2 bf = *(const ulonglong2*)(smem + OFF_W1EB +
                        (size_t)((nf1 * 32 + lane) * 16));
                    u32 bh0 = (u32)bf.x, bh1 = (u32)(bf.x >> 32);
                    u32 bl0 = (u32)bf.y, bl1 = (u32)(bf.y >> 32);
                    mma16816(dd, ehi[m*2], ehi[m*2+1], fhi[m*2], fhi[m*2+1],
                             bh0, bh1);
                    mma16816(dd, elo[m*2], elo[m*2+1], flo[m*2], flo[m*2+1],
                             bh0, bh1);
                    mma16816(dd, ehi[m*2], ehi[m*2+1], fhi[m*2], fhi[m*2+1],
                             bl0, bl1);
                    u32 h01, l01, h23, l23;
                    split2(fmaxf(dd[0], 0.f), fmaxf(dd[1], 0.f), h01, l01);
                    split2(fmaxf(dd[2], 0.f), fmaxf(dd[3], 0.f), h23, l23);
                    Ah[m][nfo * 2 + 0] = h01;  Al[m][nfo * 2 + 0] = l01;
                    Ah[m][nfo * 2 + 1] = h23;  Al[m][nfo * 2 + 1] = l23;
                }
            }
            // GEMM2: h1 @ W2
            #pragma unroll
            for (int nf = 0; nf < 8; nf++) {
                ulonglong2 bf = *(const ulonglong2*)(smem + OFF_BFRAG +
                    (size_t)((((ch * 8 + kb) * 8 + nf) * 32 + lane) * 16));
                u32 bh0 = (u32)bf.x, bh1 = (u32)(bf.x >> 32);
                u32 bl0 = (u32)bf.y, bl1 = (u32)(bf.y >> 32);
                #pragma unroll
                for (int m = 0; m < 2; m++) {
                    mma16816(d[m][nf], Ah[m][0], Ah[m][1], Ah[m][2], Ah[m][3],
                             bh0, bh1);                               // hi*hi
                    mma16816(d[m][nf], Al[m][0], Al[m][1], Al[m][2], Al[m][3],
                             bh0, bh1);                               // lo*hi
                    mma16816(d[m][nf], Ah[m][0], Ah[m][1], Ah[m][2], Ah[m][3],
                             bl0, bl1);                               // hi*lo
                }
            }
        }

        // ---- epilogue: relu(D + b2) . W3 ----
        float s[4] = {0.f, 0.f, 0.f, 0.f};
        #pragma unroll
        for (int nf = 0; nf < 8; nf++) {
            float4 bw = *(const float4*)(smem + OFF_BW +
                                         (ch * 32 + nf * 4 + q) * 16);
            #pragma unroll
            for (int m = 0; m < 2; m++) {
                s[m*2]   += fmaxf(d[m][nf][0] + bw.x, 0.f) * bw.z +
                            fmaxf(d[m][nf][1] + bw.y, 0.f) * bw.w;
                s[m*2+1] += fmaxf(d[m][nf][2] + bw.x, 0.f) * bw.z +
                            fmaxf(d[m][nf][3] + bw.y, 0.f) * bw.w;
            }
        }
        #pragma unroll
        for (int i = 0; i < 4; i++) {
            s[i] += __shfl_xor_sync(0xFFFFFFFFu, s[i], 1);
            s[i] += __shfl_xor_sync(0xFFFFFFFFu, s[i], 2);
        }
        if (q == 0) {
            #pragma unroll
            for (int i = 0; i < 4; i++) {
                int rr = mbW * 32 + (i >> 1) * 16 + ((i & 1) << 3) + g;
                smf[(OFF_PART >> 2) + ch * 256 + rr] = s[i];
            }
        }
        __syncthreads();

        if (tid < kM) {
            float a = smf[(OFF_PART >> 2) + tid] +
                      smf[(OFF_PART >> 2) + 256 + tid] + b3v;
            act_c = a;
            out[(size_t)(rowBase + tid) * kT + t] = a;
        }
        // env(t+1) written by the same tid<256 threads after the top-of-loop
        // path; other warps re-block at the next __syncthreads().
    }
}

extern "C" void kernel_launch(void* const* d_in, const int* in_sizes, int n_in,
                              void* d_out, int out_size)
{
    (void)in_sizes; (void)n_in; (void)out_size;
    const float* proj  = (const float*)d_in[0];
    const float* idm   = (const float*)d_in[1];
    const float* merg  = (const float*)d_in[2];
    const float* W1    = (const float*)d_in[3];
    const float* b1    = (const float*)d_in[4];
    const float* W2    = (const float*)d_in[5];
    const float* b2    = (const float*)d_in[6];
    const float* W3    = (const float*)d_in[7];
    const float* b3    = (const float*)d_in[8];
    const float* smean = (const float*)d_in[9];
    const float* svar  = (const float*)d_in[10];
    float* out = (float*)d_out;

    cudaFuncSetAttribute(fsim_mma, cudaFuncAttributeMaxDynamicSharedMemorySize,
                         SMEM_BYTES);
    fsim_mma<<<kB / kM, kThreads, SMEM_BYTES>>>(
        proj, idm, merg, W1, b1, W2, b2, W3, b3, smean, svar, out);
}

// round 7
// speedup vs baseline: 1.1936x; 1.1936x over previous
#include <cuda_runtime.h>
#include <cuda_fp16.h>
#include <cstddef>

// ForwardSim, fully tensorized HMMA (sm_103 baseline mma.sync, 3-term fp16).
// R7: R4 topology (kM=64, 256thr, 2 CTA/SM, grid 512 = 86% wave util) +
// R6 tensorized GEMM1 (env@W1e on tensor pipe, accumulators seeded from
// fragment-native projAcc) + software-pipelined kb loop: GEMM1-mma(kb+1)
// issues before GEMM2(kb), splits after, so HMMA latency is covered.

using u32 = unsigned int;
using u64 = unsigned long long;

namespace {
constexpr int kB = 32768, kT = 50, kH = 128, kM = 64, kThreads = 256;

constexpr int OFF_BFRAG = 0;        // 65536: W2 frags [ch][kb][nf][lane] 16B
constexpr int OFF_PACC  = 65536;    // 32768: projAcc frags [m16][nf1][lane] 16B
constexpr int OFF_W1EB  = 98304;    // 8192:  W1e B-frags [nf1][lane] 16B
constexpr int OFF_ENV   = 106496;   // 3328:  64 x 13 f32
constexpr int OFF_BW    = 109824;   // 1024:  (b2 pair, W3 pair) per col pair
constexpr int OFF_PART  = 110848;   // 512:   2 x 64 partials
constexpr int OFF_SC    = 111360;   // 64
constexpr int SMEM_BYTES = 111424;
constexpr int OFF_W1P   = 0;        // phase alias in BFRAG: W1[0:64] natural
} // namespace

__device__ __forceinline__ u64 pack_dup(float v) {
    u64 r; asm("mov.b64 %0, {%1, %1};" : "=l"(r) : "f"(v)); return r;
}
__device__ __forceinline__ u64 pack2(float a, float b) {
    u64 r; asm("mov.b64 %0, {%1, %2};" : "=l"(r) : "f"(a), "f"(b)); return r;
}
__device__ __forceinline__ void unpack2(u64 v, float& a, float& b) {
    asm("mov.b64 {%0, %1}, %2;" : "=f"(a), "=f"(b) : "l"(v));
}
__device__ __forceinline__ u64 fma2(u64 a, u64 b, u64 c) {
    u64 d; asm("fma.rn.f32x2 %0, %1, %2, %3;" : "=l"(d) : "l"(a), "l"(b), "l"(c));
    return d;
}
__device__ __forceinline__ void split2(float f0, float f1, u32& hi, u32& lo) {
    __half h0 = __float2half_rn(f0), h1 = __float2half_rn(f1);
    __half2 hh = __halves2half2(h0, h1);
    hi = reinterpret_cast<u32&>(hh);
    __half2 ll = __floats2half2_rn(f0 - __half2float(h0),
                                   f1 - __half2float(h1));
    lo = reinterpret_cast<u32&>(ll);
}
__device__ __forceinline__ void mma16816(float d[4], u32 a0, u32 a1, u32 a2,
                                         u32 a3, u32 b0, u32 b1) {
    asm volatile(
        "mma.sync.aligned.m16n8k16.row.col.f32.f16.f16.f32 "
        "{%0,%1,%2,%3}, {%4,%5,%6,%7}, {%8,%9}, {%0,%1,%2,%3};"
        : "+f"(d[0]), "+f"(d[1]), "+f"(d[2]), "+f"(d[3])
        : "r"(a0), "r"(a1), "r"(a2), "r"(a3), "r"(b0), "r"(b1));
}

__global__ void __launch_bounds__(kThreads, 2)
fsim_mma(const float* __restrict__ proj, const float* __restrict__ idm,
         const float* __restrict__ merg, const float* __restrict__ W1,
         const float* __restrict__ b1,   const float* __restrict__ W2,
         const float* __restrict__ b2,   const float* __restrict__ W3,
         const float* __restrict__ b3,   const float* __restrict__ smean,
         const float* __restrict__ svar, float* __restrict__ out)
{
    extern __shared__ char smem[];
    float* smf = (float*)smem;

    const int tid = threadIdx.x, wid = tid >> 5, lane = tid & 31;
    const int mbW = wid >> 1, ch = wid & 1, g = lane >> 2, q = lane & 3;
    const int rowBase = blockIdx.x * kM;

    // ---------------- phase A: stage W1[0:64] natural + tables -------------
    for (int i = tid; i < 64 * kH; i += kThreads)
        smf[(OFF_W1P >> 2) + i] = W1[i];
    if (tid < 64) {
        int c = tid * 2;
        float4 v;
        v.x = b2[c]; v.y = b2[c + 1]; v.z = W3[c]; v.w = W3[c + 1];
        *(float4*)(smem + OFF_BW + tid * 16) = v;
    }
    if (tid < 6) {
        smf[(OFF_SC >> 2) + tid]     = smean[tid];
        smf[(OFF_SC >> 2) + 8 + tid] = rsqrtf(svar[tid]);
    }
    __syncthreads();

    // -------- phase B: projAcc = proj@W1[:64]+b1 -> fragment-native fp32 ---
    for (int task = tid; task < 512; task += kThreads) {
        int r = task >> 3, cg = task & 7;   // row (0..63), 16-col group
        const float* prow = proj + (size_t)(rowBase + r) * 64;
        u64 acc[8];
        #pragma unroll
        for (int e = 0; e < 8; e++)
            acc[e] = pack2(__ldg(&b1[cg * 16 + 2 * e]),
                           __ldg(&b1[cg * 16 + 2 * e + 1]));
        #pragma unroll 4
        for (int k4 = 0; k4 < 16; k4++) {
            float4 av = __ldg((const float4*)(prow + k4 * 4));
            float avv[4] = {av.x, av.y, av.z, av.w};
            #pragma unroll
            for (int e2 = 0; e2 < 4; e2++) {
                u64 a = pack_dup(avv[e2]);
                const u64* w = (const u64*)
                    &smf[(OFF_W1P >> 2) + (k4 * 4 + e2) * 128 + cg * 16];
                #pragma unroll
                for (int e = 0; e < 8; e++) acc[e] = fma2(a, w[e], acc[e]);
            }
        }
        int m16 = r >> 4, half = (r >> 3) & 1, lrow = r & 7;
        #pragma unroll
        for (int e = 0; e < 8; e++) {
            int nf1 = cg * 2 + (e >> 2);
            int ln  = lrow * 4 + (e & 3);
            float lo_, hi_;
            unpack2(acc[e], lo_, hi_);
            *(float2*)(smem + OFF_PACC +
                       (size_t)(((m16 * 16 + nf1) * 32 + ln) * 16) + half * 8)
                = make_float2(lo_, hi_);
        }
    }
    __syncthreads();

    // -------- phase C: W2 -> fragment fp16 hi/lo (overwrites W1P) ----------
    for (int i = tid; i < 4096; i += kThreads) {
        int t  = i & 31, nf = (i >> 5) & 7, kb = (i >> 8) & 7, c2 = (i >> 11) & 1;
        int gg = t >> 2, qq = t & 3;
        int n  = c2 * 64 + nf * 8 + gg;
        int k0 = kb * 16 + qq * 2;
        float w00 = W2[(size_t)k0 * 128 + n];
        float w01 = W2[(size_t)(k0 + 1) * 128 + n];
        float w10 = W2[(size_t)(k0 + 8) * 128 + n];
        float w11 = W2[(size_t)(k0 + 9) * 128 + n];
        u32 h0, l0, h1v, l1v;
        split2(w00, w01, h0, l0);
        split2(w10, w11, h1v, l1v);
        ulonglong2 e;
        e.x = ((u64)h1v << 32) | h0;
        e.y = ((u64)l1v << 32) | l0;
        *(ulonglong2*)(smem + OFF_BFRAG +
                       (size_t)(((c2 * 8 + kb) * 8 + nf) * 32 + t) * 16) = e;
    }
    // -------- phase C2: W1e (W1 rows 64..72) -> B-frags, K=16 padded -------
    for (int i = tid; i < 512; i += kThreads) {
        int t = i & 31, nf = i >> 5;        // nf 0..15
        int gg = t >> 2, qq = t & 3;
        int n  = nf * 8 + gg;
        int k0 = qq * 2;
        float w00 = W1[(size_t)(64 + k0) * 128 + n];
        float w01 = W1[(size_t)(64 + k0 + 1) * 128 + n];
        float w10 = (qq == 0) ? W1[(size_t)72 * 128 + n] : 0.f;  // k=8 only
        u32 h0, l0, h1v, l1v;
        split2(w00, w01, h0, l0);
        split2(w10, 0.f, h1v, l1v);
        ulonglong2 e;
        e.x = ((u64)h1v << 32) | h0;
        e.y = ((u64)l1v << 32) | l0;
        *(ulonglong2*)(smem + OFF_W1EB + (size_t)(nf * 32 + t) * 16) = e;
    }
    __syncthreads();

    const float b3v = __ldg(&b3[0]);
    float ego_v = 0.f, ego_x = 0.f, act_c = 0.f;   // carry in tid<64

    // ================= timestep loop =================
    for (int t = 0; t < kT; t++) {
        // ---- env features (one thread per row) ----
        if (tid < kM) {
            const float* sp = idm + (size_t)(rowBase + tid) * (kT * 12) + t * 12;
            float4 a0 = *(const float4*)sp;
            float4 a1 = *(const float4*)(sp + 4);
            float s11 = sp[11];
            if (t == 0) { ego_v = a0.x; ego_x = a0.w; }
            else {
                ego_v = fmaf(act_c, 0.1f, ego_v);
                ego_x = ego_x + ego_v * 0.1f + act_c * 0.005f;
            }
            float ev[6];
            ev[0] = ego_v;
            ev[1] = a0.y;
            ev[2] = ego_v - a0.y;
            ev[3] = a1.x - ego_x;
            ev[4] = (ego_v - a0.z) * s11;
            ev[5] = (a1.y - ego_x) * s11 + (1.0f - s11) * 100.0f;
            #pragma unroll
            for (int j = 0; j < 6; j++)
                smf[(OFF_ENV >> 2) + tid * 13 + j] =
                    (ev[j] - smf[(OFF_SC >> 2) + j]) * smf[(OFF_SC >> 2) + 8 + j];
            const float* mp = merg + (size_t)(rowBase + tid) * (kT * 3) + t * 3;
            smf[(OFF_ENV >> 2) + tid * 13 + 6] = mp[0];
            smf[(OFF_ENV >> 2) + tid * 13 + 7] = mp[1];
            smf[(OFF_ENV >> 2) + tid * 13 + 8] = mp[2];
        }
        __syncthreads();

        // ---- env A-fragments for this warp's 2 row-slots (g, g+8) ----
        u32 ehi[2], elo[2], fhi[2], flo[2];
        #pragma unroll
        for (int p = 0; p < 2; p++) {
            int rr = mbW * 16 + p * 8 + g;
            const float* ep = &smf[(OFF_ENV >> 2) + rr * 13];
            float e0 = ep[2 * q], e1 = ep[2 * q + 1];
            float e8 = (q == 0) ? ep[8] : 0.f;
            split2(e0, e1, ehi[p], elo[p]);
            split2(e8, 0.f, fhi[p], flo[p]);
        }

        float d[8][4];
        #pragma unroll
        for (int nf = 0; nf < 8; nf++)
            d[nf][0] = d[nf][1] = d[nf][2] = d[nf][3] = 0.f;

        // GEMM1 mma for a k-block: dd[nfo][4] accumulators
        auto gemm1_mma = [&](int kb, float dd[2][4]) {
            #pragma unroll
            for (int nfo = 0; nfo < 2; nfo++) {
                int nf1 = kb * 2 + nfo;
                float4 pv = *(const float4*)(smem + OFF_PACC +
                    (size_t)(((mbW * 16 + nf1) * 32 + lane) * 16));
                dd[nfo][0] = pv.x; dd[nfo][1] = pv.y;
                dd[nfo][2] = pv.z; dd[nfo][3] = pv.w;
                ulonglong2 bf = *(const ulonglong2*)(smem + OFF_W1EB +
                    (size_t)((nf1 * 32 + lane) * 16));
                u32 bh0 = (u32)bf.x, bh1 = (u32)(bf.x >> 32);
                u32 bl0 = (u32)bf.y, bl1 = (u32)(bf.y >> 32);
                mma16816(dd[nfo], ehi[0], ehi[1], fhi[0], fhi[1], bh0, bh1);
                mma16816(dd[nfo], elo[0], elo[1], flo[0], flo[1], bh0, bh1);
                mma16816(dd[nfo], ehi[0], ehi[1], fhi[0], fhi[1], bl0, bl1);
            }
        };
        auto gemm1_split = [&](const float dd[2][4], u32 Ah[4], u32 Al[4]) {
            #pragma unroll
            for (int nfo = 0; nfo < 2; nfo++) {
                u32 h01, l01, h23, l23;
                split2(fmaxf(dd[nfo][0], 0.f), fmaxf(dd[nfo][1], 0.f), h01, l01);
                split2(fmaxf(dd[nfo][2], 0.f), fmaxf(dd[nfo][3], 0.f), h23, l23);
                Ah[nfo * 2 + 0] = h01;  Al[nfo * 2 + 0] = l01;
                Ah[nfo * 2 + 1] = h23;  Al[nfo * 2 + 1] = l23;
            }
        };

        u32 Ah[2][4], Al[2][4];
        float dd[2][4];
        gemm1_mma(0, dd);
        gemm1_split(dd, Ah[0], Al[0]);

        #pragma unroll
        for (int kb = 0; kb < 8; kb++) {
            const int cur = kb & 1, nxt = cur ^ 1;
            float ddn[2][4];
            if (kb < 7) gemm1_mma(kb + 1, ddn);   // overlap with GEMM2 below
            const char* bfp = smem + OFF_BFRAG +
                              (size_t)((ch * 8 + kb) * 8) * 512 + lane * 16;
            #pragma unroll
            for (int nf = 0; nf < 8; nf++) {
                ulonglong2 bf = *(const ulonglong2*)(bfp + nf * 512);
                u32 bh0 = (u32)bf.x, bh1 = (u32)(bf.x >> 32);
                u32 bl0 = (u32)bf.y, bl1 = (u32)(bf.y >> 32);
                mma16816(d[nf], Ah[cur][0], Ah[cur][1], Ah[cur][2], Ah[cur][3],
                         bh0, bh1);                               // hi*hi
                mma16816(d[nf], Al[cur][0], Al[cur][1], Al[cur][2], Al[cur][3],
                         bh0, bh1);                               // lo*hi
                mma16816(d[nf], Ah[cur][0], Ah[cur][1], Ah[cur][2], Ah[cur][3],
                         bl0, bl1);                               // hi*lo
            }
            if (kb < 7) gemm1_split(ddn, Ah[nxt], Al[nxt]);
        }

        // ---- epilogue: relu(D + b2) . W3 ----
        float s0 = 0.f, s1 = 0.f;
        #pragma unroll
        for (int nf = 0; nf < 8; nf++) {
            float4 bw = *(const float4*)(smem + OFF_BW +
                                         (ch * 32 + nf * 4 + q) * 16);
            s0 += fmaxf(d[nf][0] + bw.x, 0.f) * bw.z +
                  fmaxf(d[nf][1] + bw.y, 0.f) * bw.w;
            s1 += fmaxf(d[nf][2] + bw.x, 0.f) * bw.z +
                  fmaxf(d[nf][3] + bw.y, 0.f) * bw.w;
        }
        s0 += __shfl_xor_sync(0xFFFFFFFFu, s0, 1);
        s0 += __shfl_xor_sync(0xFFFFFFFFu, s0, 2);
        s1 += __shfl_xor_sync(0xFFFFFFFFu, s1, 1);
        s1 += __shfl_xor_sync(0xFFFFFFFFu, s1, 2);
        if (q == 0) {
            smf[(OFF_PART >> 2) + ch * 64 + mbW * 16 + g]     = s0;
            smf[(OFF_PART >> 2) + ch * 64 + mbW * 16 + g + 8] = s1;
        }
        __syncthreads();

        if (tid < kM) {
            float a = smf[(OFF_PART >> 2) + tid] +
                      smf[(OFF_PART >> 2) + 64 + tid] + b3v;
            act_c = a;
            out[(size_t)(rowBase + tid) * kT + t] = a;
        }
        // env(t+1) is written by the same tid<64 threads; every other warp
        // re-blocks at the next __syncthreads() before reading env.
    }
}

extern "C" void kernel_launch(void* const* d_in, const int* in_sizes, int n_in,
                              void* d_out, int out_size)
{
    (void)in_sizes; (void)n_in; (void)out_size;
    const float* proj  = (const float*)d_in[0];
    const float* idm   = (const float*)d_in[1];
    const float* merg  = (const float*)d_in[2];
    const float* W1    = (const float*)d_in[3];
    const float* b1    = (const float*)d_in[4];
    const float* W2    = (const float*)d_in[5];
    const float* b2    = (const float*)d_in[6];
    const float* W3    = (const float*)d_in[7];
    const float* b3    = (const float*)d_in[8];
    const float* smean = (const float*)d_in[9];
    const float* svar  = (const float*)d_in[10];
    float* out = (float*)d_out;

    cudaFuncSetAttribute(fsim_mma, cudaFuncAttributeMaxDynamicSharedMemorySize,
                         SMEM_BYTES);
    fsim_mma<<<kB / kM, kThreads, SMEM_BYTES>>>(
        proj, idm, merg, W1, b1, W2, b2, W3, b3, smean, svar, out);
}